// round 5
// baseline (speedup 1.0000x reference)
#include <cuda_runtime.h>
#include <math.h>
#include <stdint.h>

#define BATCH 4
#define DCH   512
#define NSEQ  1536
#define NHEAD 8
#define HDIM  64

// ---------------- scratch (device globals; no runtime allocation) ----------
__device__ float g_q[BATCH * DCH * NSEQ];
__device__ float g_k[BATCH * DCH * NSEQ];
__device__ float g_v[BATCH * DCH * NSEQ];
__device__ float g_x[BATCH * DCH * NSEQ];
__device__ float g_scores[(size_t)BATCH * NHEAD * NSEQ * NSEQ]; // 302 MB
__device__ float g_min;

// ---------------- helpers ---------------------------------------------------
__device__ __forceinline__ void atomicMinFloat(float* addr, float val) {
    if (val >= 0.0f) atomicMin((int*)addr, __float_as_int(val));
    else             atomicMax((unsigned int*)addr, __float_as_uint(val));
}

__device__ __forceinline__ uint32_t f2tf32(float f) {
    uint32_t u;
    asm("cvt.rna.tf32.f32 %0, %1;" : "=r"(u) : "f"(f));
    return u;
}

// m16n8k8 tf32 MMA, fp32 accumulate.
// A frag (16x8): a0=(g,tg) a1=(g+8,tg) a2=(g,tg+4) a3=(g+8,tg+4); g=lane>>2, tg=lane&3
// B frag (8x8):  b0=(tg,g) b1=(tg+4,g)
// C frag (16x8): c0=(g,2tg) c1=(g,2tg+1) c2=(g+8,2tg) c3=(g+8,2tg+1)
__device__ __forceinline__ void mma_tf32(float* c, const uint32_t* a, const uint32_t* b) {
    asm volatile(
        "mma.sync.aligned.m16n8k8.row.col.f32.tf32.tf32.f32 "
        "{%0,%1,%2,%3}, {%4,%5,%6,%7}, {%8,%9}, {%0,%1,%2,%3};"
        : "+f"(c[0]), "+f"(c[1]), "+f"(c[2]), "+f"(c[3])
        : "r"(a[0]), "r"(a[1]), "r"(a[2]), "r"(a[3]), "r"(b[0]), "r"(b[1]));
}

// =======================================================================
// Shared projection body: Y[o,n] (+bias) = W[o,c] X[c,n], 128x128 tile, BK=32
// 8 warps (2x4), warp tile 64x32.
// =======================================================================
__device__ __forceinline__ void proj_tile(const float* __restrict__ W,
                                          const float* __restrict__ Xb,
                                          const float* __restrict__ bias,
                                          float* __restrict__ Yb,
                                          int o0, int n0) {
    __shared__ uint32_t As[32][136];   // [k][o]
    __shared__ uint32_t Bs[32][136];   // [k][n]
    const int tid = threadIdx.x;
    const int warp = tid >> 5, lane = tid & 31;
    const int g = lane >> 2, tg = lane & 3;
    const int mo = (warp >> 2) * 64;
    const int no = (warp & 3) * 32;

    float acc[4][4][4] = {};

    for (int k0 = 0; k0 < DCH; k0 += 32) {
        #pragma unroll
        for (int r = 0; r < 4; r++) {
            int i = r * 256 + tid;
            int o = i >> 3, kq = i & 7;
            float4 w4 = *(const float4*)(W + (size_t)(o0 + o) * DCH + k0 + kq * 4);
            As[kq * 4 + 0][o] = f2tf32(w4.x);
            As[kq * 4 + 1][o] = f2tf32(w4.y);
            As[kq * 4 + 2][o] = f2tf32(w4.z);
            As[kq * 4 + 3][o] = f2tf32(w4.w);
        }
        #pragma unroll
        for (int r = 0; r < 4; r++) {
            int i = r * 256 + tid;
            int k = i >> 5, nq = i & 31;
            float4 x4 = *(const float4*)(Xb + (size_t)(k0 + k) * NSEQ + n0 + nq * 4);
            *(uint4*)&Bs[k][nq * 4] =
                make_uint4(f2tf32(x4.x), f2tf32(x4.y), f2tf32(x4.z), f2tf32(x4.w));
        }
        __syncthreads();
        #pragma unroll
        for (int kk = 0; kk < 32; kk += 8) {
            uint32_t a[4][4], bb[4][2];
            #pragma unroll
            for (int i = 0; i < 4; i++) {
                a[i][0] = As[kk + tg][mo + i * 16 + g];
                a[i][1] = As[kk + tg][mo + i * 16 + 8 + g];
                a[i][2] = As[kk + tg + 4][mo + i * 16 + g];
                a[i][3] = As[kk + tg + 4][mo + i * 16 + 8 + g];
            }
            #pragma unroll
            for (int j = 0; j < 4; j++) {
                bb[j][0] = Bs[kk + tg][no + j * 8 + g];
                bb[j][1] = Bs[kk + tg + 4][no + j * 8 + g];
            }
            #pragma unroll
            for (int i = 0; i < 4; i++)
                #pragma unroll
                for (int j = 0; j < 4; j++)
                    mma_tf32(acc[i][j], a[i], bb[j]);
        }
        __syncthreads();
    }
    #pragma unroll
    for (int i = 0; i < 4; i++) {
        int r0 = o0 + mo + i * 16 + g;
        int r1 = r0 + 8;
        float bv0 = bias[r0], bv1 = bias[r1];
        #pragma unroll
        for (int j = 0; j < 4; j++) {
            int col = n0 + no + j * 8 + 2 * tg;
            *(float2*)&Yb[(size_t)r0 * NSEQ + col] =
                make_float2(acc[i][j][0] + bv0, acc[i][j][1] + bv0);
            *(float2*)&Yb[(size_t)r1 * NSEQ + col] =
                make_float2(acc[i][j][2] + bv1, acc[i][j][3] + bv1);
        }
    }
}

// q/k/v projections in one launch: grid (12, 4, 12); z = proj*4 + batch
// Also initializes g_min (block 0), replacing a separate init launch.
__global__ __launch_bounds__(256) void gemm_proj_qkv(
    const float* __restrict__ query, const float* __restrict__ key,
    const float* __restrict__ value,
    const float* __restrict__ Wq, const float* __restrict__ Wk,
    const float* __restrict__ Wv,
    const float* __restrict__ bq, const float* __restrict__ bk,
    const float* __restrict__ bv) {
    if (blockIdx.x == 0 && blockIdx.y == 0 && blockIdx.z == 0 && threadIdx.x == 0)
        g_min = 3.402823466e38f;
    const int z = blockIdx.z, p = z >> 2, b = z & 3;
    const float* W  = (p == 0) ? Wq : (p == 1) ? Wk : Wv;
    const float* X  = ((p == 0) ? query : (p == 1) ? key : value) + (size_t)b * DCH * NSEQ;
    const float* bi = (p == 0) ? bq : (p == 1) ? bk : bv;
    float* Y = ((p == 0) ? g_q : (p == 1) ? g_k : g_v) + (size_t)b * DCH * NSEQ;
    proj_tile(W, X, bi, Y, blockIdx.y * 128, blockIdx.x * 128);
}

__global__ __launch_bounds__(256) void gemm_proj_out(const float* __restrict__ Wm,
                                                     const float* __restrict__ bm,
                                                     float* __restrict__ out) {
    const int b = blockIdx.z;
    proj_tile(Wm, g_x + (size_t)b * DCH * NSEQ, bm, out + (size_t)b * DCH * NSEQ,
              blockIdx.y * 128, blockIdx.x * 128);
}

// =======================================================================
// Merged scores + mean + min: one block owns a 128x128 (n,m) tile for a batch,
// loops over all 8 heads (K=64 each). Stores per-head raw scores (x0.125),
// accumulates the mean tile in registers (no extra mma), tracks global min.
// Mean stored RAW (no penalty; penalty added later once min is final).
// grid (12 m, 12 n, 4 b), 256 threads, 8 warps (2x4), warp tile 64x32
// =======================================================================
__global__ __launch_bounds__(256) void scores_mean_tc(float* __restrict__ out_mean) {
    __shared__ uint32_t As[32][136];   // [d][n]
    __shared__ uint32_t Bs[32][136];   // [d][m]
    const int b = blockIdx.z;
    const int n0 = blockIdx.y * 128, m0 = blockIdx.x * 128;
    const float* qb = g_q + (size_t)b * DCH * NSEQ;
    const float* kb = g_k + (size_t)b * DCH * NSEQ;
    const int tid = threadIdx.x;
    const int warp = tid >> 5, lane = tid & 31;
    const int g = lane >> 2, tg = lane & 3;
    const int mo = (warp >> 2) * 64;
    const int no = (warp & 3) * 32;

    float macc[4][4][4] = {};
    float lmin = 3.402823466e38f;

    for (int h = 0; h < NHEAD; h++) {
        float acc[4][4][4] = {};
        for (int k0 = 0; k0 < HDIM; k0 += 32) {
            #pragma unroll
            for (int r = 0; r < 4; r++) {
                int i = r * 256 + tid;
                int d = i >> 5, nq = i & 31;
                size_t roff = (size_t)((k0 + d) * 8 + h) * NSEQ;
                float4 q4 = *(const float4*)(qb + roff + n0 + nq * 4);
                float4 k4 = *(const float4*)(kb + roff + m0 + nq * 4);
                *(uint4*)&As[d][nq * 4] =
                    make_uint4(f2tf32(q4.x), f2tf32(q4.y), f2tf32(q4.z), f2tf32(q4.w));
                *(uint4*)&Bs[d][nq * 4] =
                    make_uint4(f2tf32(k4.x), f2tf32(k4.y), f2tf32(k4.z), f2tf32(k4.w));
            }
            __syncthreads();
            #pragma unroll
            for (int kk = 0; kk < 32; kk += 8) {
                uint32_t a[4][4], bb[4][2];
                #pragma unroll
                for (int i = 0; i < 4; i++) {
                    a[i][0] = As[kk + tg][mo + i * 16 + g];
                    a[i][1] = As[kk + tg][mo + i * 16 + 8 + g];
                    a[i][2] = As[kk + tg + 4][mo + i * 16 + g];
                    a[i][3] = As[kk + tg + 4][mo + i * 16 + 8 + g];
                }
                #pragma unroll
                for (int j = 0; j < 4; j++) {
                    bb[j][0] = Bs[kk + tg][no + j * 8 + g];
                    bb[j][1] = Bs[kk + tg + 4][no + j * 8 + g];
                }
                #pragma unroll
                for (int i = 0; i < 4; i++)
                    #pragma unroll
                    for (int j = 0; j < 4; j++)
                        mma_tf32(acc[i][j], a[i], bb[j]);
            }
            __syncthreads();
        }
        // per-head epilogue: scale, store, fold into mean acc, track min
        const size_t sbase = (size_t)(b * NHEAD + h) * NSEQ * NSEQ;
        #pragma unroll
        for (int i = 0; i < 4; i++) {
            int r0 = n0 + mo + i * 16 + g;
            int r1 = r0 + 8;
            #pragma unroll
            for (int j = 0; j < 4; j++) {
                int col = m0 + no + j * 8 + 2 * tg;
                float s0 = acc[i][j][0] * 0.125f, s1 = acc[i][j][1] * 0.125f;
                float s2 = acc[i][j][2] * 0.125f, s3 = acc[i][j][3] * 0.125f;
                lmin = fminf(lmin, fminf(fminf(s0, s1), fminf(s2, s3)));
                *(float2*)&g_scores[sbase + (size_t)r0 * NSEQ + col] = make_float2(s0, s1);
                *(float2*)&g_scores[sbase + (size_t)r1 * NSEQ + col] = make_float2(s2, s3);
                macc[i][j][0] += acc[i][j][0];
                macc[i][j][1] += acc[i][j][1];
                macc[i][j][2] += acc[i][j][2];
                macc[i][j][3] += acc[i][j][3];
            }
        }
    }
    // mean tile: (1/8) * sum_h (acc_h / 8) = sum_h acc_h / 64
    float* om = out_mean + (size_t)b * NSEQ * NSEQ;
    #pragma unroll
    for (int i = 0; i < 4; i++) {
        int r0 = n0 + mo + i * 16 + g;
        int r1 = r0 + 8;
        #pragma unroll
        for (int j = 0; j < 4; j++) {
            int col = m0 + no + j * 8 + 2 * tg;
            *(float2*)&om[(size_t)r0 * NSEQ + col] =
                make_float2(macc[i][j][0] * 0.015625f, macc[i][j][1] * 0.015625f);
            *(float2*)&om[(size_t)r1 * NSEQ + col] =
                make_float2(macc[i][j][2] * 0.015625f, macc[i][j][3] * 0.015625f);
        }
    }
    // block min -> global min
    #pragma unroll
    for (int o = 16; o > 0; o >>= 1)
        lmin = fminf(lmin, __shfl_xor_sync(0xFFFFFFFFu, lmin, o));
    __shared__ float red[8];
    if (lane == 0) red[warp] = lmin;
    __syncthreads();
    if (warp == 0) {
        float v = (lane < 8) ? red[lane] : 3.402823466e38f;
        #pragma unroll
        for (int o = 4; o > 0; o >>= 1)
            v = fminf(v, __shfl_xor_sync(0xFFFFFFFFu, v, o));
        if (lane == 0) atomicMinFloat(&g_min, v);
    }
}

// =======================================================================
// Penalty pass: out_mean[b,n,m] += (mask ? 0 : g_min-20). grid (2304, 4), 256 thr
// =======================================================================
__global__ __launch_bounds__(256) void penalty_kernel(const int* __restrict__ maskw,
                                                      float* __restrict__ out_mean) {
    const int b = blockIdx.y;
    const size_t i = ((size_t)blockIdx.x * 256 + threadIdx.x) * 4;
    const float minv = g_min - 20.0f;
    int4 mk = *(const int4*)(maskw + i);
    float4* p = (float4*)(out_mean + (size_t)b * NSEQ * NSEQ + i);
    float4 v = *p;
    v.x += mk.x ? 0.0f : minv;
    v.y += mk.y ? 0.0f : minv;
    v.z += mk.z ? 0.0f : minv;
    v.w += mk.w ? 0.0f : minv;
    *p = v;
}

// =======================================================================
// Fused softmax + PV (max-free): x = (sum_m e_{nm} v_m) / (sum_m e_{nm}),
// e = exp(s + pen). Single pass over scores. BK=32, warp 32n x 32d.
// grid (12, 1, 32), 256 threads
// =======================================================================
__global__ __launch_bounds__(256) void attn_pv_softmax_tc(const int* __restrict__ maskw) {
    __shared__ __align__(16) char smemraw[34816];
    uint32_t (*As)[136] = (uint32_t(*)[136])smemraw;               // exp(s) tf32, [m][n] 32x136
    uint32_t (*Bs)[72]  = (uint32_t(*)[72])(smemraw + 17408);      // v tf32, [m][dim] 32x72
    float    (*Xs)[132] = (float(*)[132])smemraw;                  // out stage [dim][n] 64x132
    float*   rowsum2    = (float*)(smemraw + 33792);               // [2][128]

    const int z = blockIdx.z, b = z >> 3, h = z & 7;
    const int n0 = blockIdx.x * 128;
    const float* sb = g_scores + (size_t)z * NSEQ * NSEQ;
    const float* vb = g_v + (size_t)b * DCH * NSEQ + (size_t)h * NSEQ;
    float*       xb = g_x + (size_t)b * DCH * NSEQ + (size_t)h * NSEQ;
    const int tid = threadIdx.x;
    const int warp = tid >> 5, lane = tid & 31;
    const int g = lane >> 2, tg = lane & 3;
    const int mo = (warp >> 1) * 32;   // n-origin within block
    const int no = (warp & 1) * 32;    // dim-origin within block
    const int myn = tid & 127, half = tid >> 7;
    const float minv = g_min - 20.0f;

    float acc[2][4][4] = {};
    float rsum = 0.0f;

    for (int k0 = 0; k0 < NSEQ; k0 += 32) {
        // scores tile + mask -> exp -> As[m][n]
        #pragma unroll
        for (int r = 0; r < 4; r++) {
            int i = r * 256 + tid;
            int n = i >> 3, mq = i & 7;
            size_t goff = (size_t)(n0 + n) * NSEQ + k0 + mq * 4;
            float4 s4 = *(const float4*)(sb + goff);
            int4   mk = *(const int4*)(maskw + goff);
            float e0 = __expf(s4.x + (mk.x ? 0.f : minv));
            float e1 = __expf(s4.y + (mk.y ? 0.f : minv));
            float e2 = __expf(s4.z + (mk.z ? 0.f : minv));
            float e3 = __expf(s4.w + (mk.w ? 0.f : minv));
            As[mq * 4 + 0][n] = f2tf32(e0);
            As[mq * 4 + 1][n] = f2tf32(e1);
            As[mq * 4 + 2][n] = f2tf32(e2);
            As[mq * 4 + 3][n] = f2tf32(e3);
        }
        // V tile -> Bs[m][dim]
        #pragma unroll
        for (int r = 0; r < 2; r++) {
            int i = r * 256 + tid;
            int dim = i >> 3, mq = i & 7;
            float4 v4 = *(const float4*)(vb + (size_t)dim * 8 * NSEQ + k0 + mq * 4);
            Bs[mq * 4 + 0][dim] = f2tf32(v4.x);
            Bs[mq * 4 + 1][dim] = f2tf32(v4.y);
            Bs[mq * 4 + 2][dim] = f2tf32(v4.z);
            Bs[mq * 4 + 3][dim] = f2tf32(v4.w);
        }
        __syncthreads();
        // row-sum partial (tf32 bits are valid fp32; each (half, n) owned by one thread)
        #pragma unroll
        for (int m = 0; m < 16; m++)
            rsum += __uint_as_float(As[half * 16 + m][myn]);
        // PV mma
        #pragma unroll
        for (int kk = 0; kk < 32; kk += 8) {
            uint32_t a[2][4], bb[4][2];
            #pragma unroll
            for (int i = 0; i < 2; i++) {
                a[i][0] = As[kk + tg][mo + i * 16 + g];
                a[i][1] = As[kk + tg][mo + i * 16 + 8 + g];
                a[i][2] = As[kk + tg + 4][mo + i * 16 + g];
                a[i][3] = As[kk + tg + 4][mo + i * 16 + 8 + g];
            }
            #pragma unroll
            for (int j = 0; j < 4; j++) {
                bb[j][0] = Bs[kk + tg][no + j * 8 + g];
                bb[j][1] = Bs[kk + tg + 4][no + j * 8 + g];
            }
            #pragma unroll
            for (int i = 0; i < 2; i++)
                #pragma unroll
                for (int j = 0; j < 4; j++)
                    mma_tf32(acc[i][j], a[i], bb[j]);
        }
        __syncthreads();
    }
    rowsum2[half * 128 + myn] = rsum;
    __syncthreads();
    // normalize + stage to Xs[dim][n] (Xs aliases As/Bs; all reads done)
    #pragma unroll
    for (int i = 0; i < 2; i++) {
        int r0 = mo + i * 16 + g;
        float inv0 = 1.0f / (rowsum2[r0] + rowsum2[128 + r0]);
        float inv8 = 1.0f / (rowsum2[r0 + 8] + rowsum2[128 + r0 + 8]);
        #pragma unroll
        for (int j = 0; j < 4; j++) {
            int d0 = no + j * 8 + 2 * tg;
            Xs[d0][r0]         = acc[i][j][0] * inv0;
            Xs[d0 + 1][r0]     = acc[i][j][1] * inv0;
            Xs[d0][r0 + 8]     = acc[i][j][2] * inv8;
            Xs[d0 + 1][r0 + 8] = acc[i][j][3] * inv8;
        }
    }
    __syncthreads();
    #pragma unroll
    for (int r = 0; r < 8; r++) {
        int i = r * 256 + tid;
        int dim = i >> 5, nq = i & 31;
        *(float4*)(xb + (size_t)dim * 8 * NSEQ + n0 + nq * 4) = *(float4*)&Xs[dim][nq * 4];
    }
}

// ---------------- launch ----------------------------------------------------
extern "C" void kernel_launch(void* const* d_in, const int* in_sizes, int n_in,
                              void* d_out, int out_size) {
    const float* query = (const float*)d_in[0];
    const float* key   = (const float*)d_in[1];
    const float* value = (const float*)d_in[2];
    // d_in[3] = dist (unused by the reference)
    const int*   maskw = (const int*)d_in[4];
    const float* Wq = (const float*)d_in[5];
    const float* bq = (const float*)d_in[6];
    const float* Wk = (const float*)d_in[7];
    const float* bk = (const float*)d_in[8];
    const float* Wv = (const float*)d_in[9];
    const float* bv = (const float*)d_in[10];
    const float* Wm = (const float*)d_in[11];
    const float* bm = (const float*)d_in[12];

    float* out      = (float*)d_out;                      // [B, D, N]
    float* out_mean = out + (size_t)BATCH * DCH * NSEQ;   // [B, N, N]

    dim3 grid_qkv(NSEQ / 128, DCH / 128, BATCH * 3);
    dim3 grid_proj(NSEQ / 128, DCH / 128, BATCH);
    dim3 grid_sm(NSEQ / 128, NSEQ / 128, BATCH);
    dim3 grid_pen(NSEQ * NSEQ / 1024, BATCH);
    dim3 grid_pv(NSEQ / 128, 1, BATCH * NHEAD);

    gemm_proj_qkv<<<grid_qkv, 256>>>(query, key, value, Wq, Wk, Wv, bq, bk, bv);
    scores_mean_tc<<<grid_sm, 256>>>(out_mean);
    penalty_kernel<<<grid_pen, 256>>>(maskw, out_mean);
    attn_pv_softmax_tc<<<grid_pv, 256>>>(maskw);
    gemm_proj_out<<<grid_proj, 256>>>(Wm, bm, out);
}